// round 12
// baseline (speedup 1.0000x reference)
#include <cuda_runtime.h>
#include <math.h>
#include <stdint.h>

#define IMG_H 240
#define IMG_W 320
#define NV 12288
#define NF 4096
#define NCH 11
#define TSZ 16
#define CHF 128      // faces per smem chunk
#define SLICES 4
#define FPS (NF / SLICES)   // 1024 faces per slice

// ---------------- device scratch (no allocations allowed) ----------------
__device__ float g_vn[NV * 3];                 // vertex normal accumulators
__device__ float g_px[NV], g_py[NV], g_pz[NV]; // screen coords + ndc z
__device__ float g_iw[NV], g_wcl[NV];          // inv_w and clip w
__device__ float g_vcol[NV * NCH];             // per-vertex 11-ch color

// hot face data, SoA float4
__device__ float4 g_hA[NF];   // bx, by, cx, cy
__device__ float4 g_hB[NF];   // d0x, d0y, d1x, d1y
__device__ float4 g_hC[NF];   // inv_area, z0, z1, z2
__device__ float4 g_iw4[NF];  // iw0, iw1, iw2, pad   (cold, resolve only)
__device__ float4 g_bb4[NF];  // bbox x0, x1, y0, y1

__device__ unsigned long long g_zkey[IMG_H * IMG_W];  // (ordered_depth<<32)|faceidx

struct Proj { float m[16]; };

__device__ __forceinline__ unsigned int ford(float d) {
    unsigned int b = __float_as_uint(d);
    return (b & 0x80000000u) ? ~b : (b | 0x80000000u);   // monotone float->uint
}

// ---------------- kernels ----------------
__global__ void k_facenorm(const float* __restrict__ verts,
                           const int* __restrict__ faces) {
    int f = blockIdx.x * blockDim.x + threadIdx.x;
    if (f >= NF) return;
    int i0 = faces[3 * f + 0], i1 = faces[3 * f + 1], i2 = faces[3 * f + 2];
    float ax = verts[3 * i0], ay = verts[3 * i0 + 1], az = verts[3 * i0 + 2];
    float bx = verts[3 * i1], by = verts[3 * i1 + 1], bz = verts[3 * i1 + 2];
    float cx = verts[3 * i2], cy = verts[3 * i2 + 1], cz = verts[3 * i2 + 2];
    float e1x = bx - ax, e1y = by - ay, e1z = bz - az;
    float e2x = cx - ax, e2y = cy - ay, e2z = cz - az;
    float nx = e1y * e2z - e1z * e2y;
    float ny = e1z * e2x - e1x * e2z;
    float nz = e1x * e2y - e1y * e2x;
    float nrm = sqrtf(nx * nx + ny * ny + nz * nz);
    nrm = fmaxf(nrm, 1e-12f);
    nx /= nrm; ny /= nrm; nz /= nrm;
    atomicAdd(&g_vn[3 * i0 + 0], nx); atomicAdd(&g_vn[3 * i0 + 1], ny); atomicAdd(&g_vn[3 * i0 + 2], nz);
    atomicAdd(&g_vn[3 * i1 + 0], nx); atomicAdd(&g_vn[3 * i1 + 1], ny); atomicAdd(&g_vn[3 * i1 + 2], nz);
    atomicAdd(&g_vn[3 * i2 + 0], nx); atomicAdd(&g_vn[3 * i2 + 1], ny); atomicAdd(&g_vn[3 * i2 + 2], nz);
}

__global__ void k_vertex(const float* __restrict__ verts,
                         const float* __restrict__ pose, Proj P) {
    int v = blockIdx.x * blockDim.x + threadIdx.x;
    if (v >= NV) return;
    float x = verts[3 * v], y = verts[3 * v + 1], z = verts[3 * v + 2];
    float p[16];
    #pragma unroll
    for (int i = 0; i < 16; i++) p[i] = pose[i];

    float wx = p[0] * x + p[1] * y + p[2]  * z + p[3];
    float wy = p[4] * x + p[5] * y + p[6]  * z + p[7];
    float wz = p[8] * x + p[9] * y + p[10] * z + p[11];
    float cam[4];
    cam[0] = wx; cam[1] = -wy; cam[2] = -wz;
    cam[3] = p[12] * x + p[13] * y + p[14] * z + p[15];
    float clip[4];
    #pragma unroll
    for (int j = 0; j < 4; j++) {
        clip[j] = P.m[4 * j + 0] * cam[0] + P.m[4 * j + 1] * cam[1]
                + P.m[4 * j + 2] * cam[2] + P.m[4 * j + 3] * cam[3];
    }
    float wc = clip[3];
    float denw = (fabsf(wc) > 1e-9f) ? wc : 1e-9f;
    float iw = 1.0f / denw;
    float n0 = clip[0] * iw, n1 = clip[1] * iw, n2 = clip[2] * iw;
    g_px[v]  = (n0 + 1.0f) * 0.5f * (float)IMG_W;
    g_py[v]  = (1.0f - n1) * 0.5f * (float)IMG_H;
    g_pz[v]  = n2;
    g_iw[v]  = iw;
    g_wcl[v] = wc;

    float vx = g_vn[3 * v], vy = g_vn[3 * v + 1], vz = g_vn[3 * v + 2];
    float nn = sqrtf(vx * vx + vy * vy + vz * vz);
    nn = fmaxf(nn, 1e-12f);
    vx /= nn; vy /= nn; vz /= nn;

    float* col = &g_vcol[v * NCH];
    col[0] = 1.0f;
    col[1] = wx; col[2] = wy; col[3] = wz;
    col[4] = vx; col[5] = vy; col[6] = vz;
    col[7] = x;  col[8] = y;  col[9] = z; col[10] = 1.0f;
}

__global__ void k_facesetup(const int* __restrict__ faces) {
    int f = blockIdx.x * blockDim.x + threadIdx.x;
    if (f >= NF) return;
    int i0 = faces[3 * f + 0], i1 = faces[3 * f + 1], i2 = faces[3 * f + 2];
    float ax = g_px[i0], ay = g_py[i0];
    float bx = g_px[i1], by = g_py[i1];
    float cx = g_px[i2], cy = g_py[i2];
    bool wok = (g_wcl[i0] > 1e-6f) && (g_wcl[i1] > 1e-6f) && (g_wcl[i2] > 1e-6f);
    float area = (bx - ax) * (cy - ay) - (by - ay) * (cx - ax);
    bool areaok = fabsf(area) > 1e-12f;
    float inv_area = 1.0f / (areaok ? area : 1e-12f);
    bool valid = areaok && wok;

    g_hA[f] = make_float4(bx, by, cx, cy);
    g_hB[f] = make_float4(cy - by, cx - bx, ay - cy, ax - cx);
    g_hC[f] = make_float4(valid ? inv_area : 0.0f,
                          valid ? g_pz[i0] : 3e9f,
                          valid ? g_pz[i1] : 3e9f,
                          valid ? g_pz[i2] : 3e9f);
    g_iw4[f] = make_float4(g_iw[i0], g_iw[i1], g_iw[i2], 0.0f);

    // Reference e0 = -wA, e1 = -wB, e2 = 2 - wC (true barycentrics w):
    // drawn region = triangle reflected through C: {C, 2C-A, 2C-B}.
    float4 bb;
    if (valid) {
        float rax = 2.0f * cx - ax, ray = 2.0f * cy - ay;
        float rbx = 2.0f * cx - bx, rby = 2.0f * cy - by;
        bb.x = fminf(cx, fminf(rax, rbx)) - 0.5f;
        bb.y = fmaxf(cx, fmaxf(rax, rbx)) + 0.5f;
        bb.z = fminf(cy, fminf(ray, rby)) - 0.5f;
        bb.w = fmaxf(cy, fmaxf(ray, rby)) + 0.5f;
    } else {
        bb.x = 1e30f; bb.y = -1e30f; bb.z = 1e30f; bb.w = -1e30f;
    }
    g_bb4[f] = bb;
}

__global__ __launch_bounds__(TSZ * TSZ) void k_raster() {
    __shared__ float4 sA[CHF], sB[CHF], sC[CHF], sbb[CHF];

    int tx = threadIdx.x, ty = threadIdx.y;
    int x = blockIdx.x * TSZ + tx;
    int y = blockIdx.y * TSZ + ty;
    float X = (float)x + 0.5f, Y = (float)y + 0.5f;
    int tid = ty * TSZ + tx;
    int lane = tid & 31;
    int warp = tid >> 5;          // warp covers rows {2w, 2w+1}

    float tX0 = (float)(blockIdx.x * TSZ) + 0.5f, tX1 = tX0 + (float)(TSZ - 1);
    float wY0 = (float)(blockIdx.y * TSZ + warp * 2) + 0.5f;
    float wY1 = wY0 + 1.0f;

    int fbeg = blockIdx.z * FPS;

    float best = 1e9f;
    int bf = -1;

    for (int base = fbeg; base < fbeg + FPS; base += CHF) {
        // stage chunk: 128 faces * 4 float4 = 512 float4, 2 per thread
        if (tid < CHF) { sA[tid] = g_hA[base + tid]; sbb[tid] = g_bb4[base + tid]; }
        else { int t = tid - CHF; sB[t] = g_hB[base + t]; sC[t] = g_hC[base + t]; }
        #pragma unroll
        for (int r = 0; r < 2; r++) {
            int t = tid; // second half
            (void)r;
        }
        // remaining halves
        if (tid < CHF) { sB[tid] = g_hB[base + tid]; }
        else { int t = tid - CHF; sA[t] = g_hA[base + t]; sbb[t] = g_bb4[base + t]; }
        if (tid < CHF) { sC[tid] = g_hC[base + tid]; }
        __syncthreads();

        #pragma unroll
        for (int sub = 0; sub < CHF; sub += 32) {
            float4 bb = sbb[sub + lane];
            bool hit = !(bb.y < tX0 || bb.x > tX1 || bb.w < wY0 || bb.z > wY1);
            unsigned m = __ballot_sync(0xffffffffu, hit);
            while (m) {
                int j = sub + (__ffs(m) - 1);
                m &= m - 1;
                float4 A = sA[j], B = sB[j], C = sC[j];   // warp-broadcast LDS
                float e0 = ((X - A.x) * B.x - (Y - A.y) * B.y) * C.x;
                float e1 = ((X - A.z) * B.z - (Y - A.w) * B.w) * C.x;
                float e2 = 1.0f - e0 - e1;
                float depth = e0 * C.y + e1 * C.z + e2 * C.w;
                bool inside = (e0 >= 0.0f) & (e1 >= 0.0f) & (e2 >= 0.0f)
                            & (depth >= -1.0f) & (depth <= 1.0f);
                if (inside && depth < best) { best = depth; bf = base + j; }
            }
        }
        __syncthreads();
    }

    if (bf >= 0) {
        unsigned long long key = ((unsigned long long)ford(best) << 32) | (unsigned)bf;
        atomicMin(&g_zkey[(size_t)y * IMG_W + x], key);
    }
}

__global__ void k_resolve(const int* __restrict__ faces, float* __restrict__ out) {
    int i = blockIdx.x * blockDim.x + threadIdx.x;
    if (i >= IMG_H * IMG_W) return;
    unsigned long long key = g_zkey[i];
    float col[NCH];
    if (key != 0xFFFFFFFFFFFFFFFFull) {
        int bf = (int)(key & 0xFFFFFFFFu);
        int x = i % IMG_W, y = i / IMG_W;
        float X = (float)x + 0.5f, Y = (float)y + 0.5f;
        float4 A = g_hA[bf], B = g_hB[bf], C = g_hC[bf], W = g_iw4[bf];
        float e0 = ((X - A.x) * B.x - (Y - A.y) * B.y) * C.x;
        float e1 = ((X - A.z) * B.z - (Y - A.w) * B.w) * C.x;
        float e2 = 1.0f - e0 - e1;
        float p0 = e0 * W.x, p1 = e1 * W.y, p2 = e2 * W.z;
        float den = p0 + p1 + p2;
        den = (fabsf(den) > 1e-12f) ? den : 1e-12f;
        float w0 = p0 / den, w1 = p1 / den, w2 = p2 / den;
        int i0 = faces[3 * bf + 0], i1 = faces[3 * bf + 1], i2 = faces[3 * bf + 2];
        const float* c0 = &g_vcol[i0 * NCH];
        const float* c1 = &g_vcol[i1 * NCH];
        const float* c2 = &g_vcol[i2 * NCH];
        #pragma unroll
        for (int c = 0; c < NCH; c++)
            col[c] = w0 * c0[c] + w1 * c1[c] + w2 * c2[c];
    } else {
        #pragma unroll
        for (int c = 0; c < NCH; c++) col[c] = 0.0f;
    }
    float* o = out + (size_t)i * NCH;
    #pragma unroll
    for (int c = 0; c < NCH; c++) o[c] = col[c];
}

// ---------------- host ----------------
static Proj build_proj_host() {
    const double fx = 286.2057, sk = 0.0, cxx = 162.6306;
    const double fy = 286.7852, cyy = 121.0245;
    const double w = IMG_W, h = IMG_H;
    const double nc = 0.1, fc = 10.0;
    double q  = -(fc + nc) / (fc - nc);
    double qn = -2.0 * fc * nc / (fc - nc);
    double m[4][4] = {
        {2.0 * fx / w, -2.0 * sk / w, (-2.0 * cxx + w) / w, 0.0},
        {0.0, -2.0 * fy / h, (-2.0 * cyy + h) / h, 0.0},
        {0.0, 0.0, q, qn},
        {0.0, 0.0, -1.0, 0.0}
    };
    for (int k = 0; k < 4; k++) m[1][k] *= -1.0;
    Proj P;
    for (int j = 0; j < 4; j++)
        for (int k = 0; k < 4; k++)
            P.m[4 * j + k] = (float)m[j][k];
    return P;
}

extern "C" void kernel_launch(void* const* d_in, const int* in_sizes, int n_in,
                              void* d_out, int out_size) {
    const float* verts = nullptr;
    const int*   faces = nullptr;
    const float* pose  = nullptr;
    for (int i = 0; i < n_in; i++) {
        if (in_sizes[i] == NV * 3)       verts = (const float*)d_in[i];
        else if (in_sizes[i] == NF * 3)  faces = (const int*)d_in[i];
        else if (in_sizes[i] == 16)      pose  = (const float*)d_in[i];
    }
    float* out = (float*)d_out;    // (1, 240, 320, 11)
    (void)out_size;

    Proj P = build_proj_host();

    void* vn_ptr = nullptr;
    void* zk_ptr = nullptr;
    cudaGetSymbolAddress(&vn_ptr, g_vn);
    cudaGetSymbolAddress(&zk_ptr, g_zkey);
    cudaMemsetAsync(vn_ptr, 0, NV * 3 * sizeof(float));
    cudaMemsetAsync(zk_ptr, 0xFF, IMG_H * IMG_W * sizeof(unsigned long long));

    k_facenorm<<<(NF + 127) / 128, 128>>>(verts, faces);
    k_vertex<<<(NV + 255) / 256, 256>>>(verts, pose, P);
    k_facesetup<<<(NF + 127) / 128, 128>>>(faces);
    dim3 grid(IMG_W / TSZ, IMG_H / TSZ, SLICES);
    dim3 blk(TSZ, TSZ);
    k_raster<<<grid, blk>>>();
    k_resolve<<<(IMG_H * IMG_W + 255) / 256, 256>>>(faces, out);
}

// round 13
// speedup vs baseline: 1.0149x; 1.0149x over previous
#include <cuda_runtime.h>
#include <math.h>
#include <stdint.h>

#define IMG_H 240
#define IMG_W 320
#define NV 12288
#define NF 4096
#define NCH 11
#define TSZ 16
#define CHF 128      // faces per smem chunk
#define SLICES 4
#define FPS (NF / SLICES)   // 1024 faces per slice

// ---------------- device scratch (no allocations allowed) ----------------
__device__ float g_vn[NV * 3];                 // vertex normal accumulators
__device__ float g_px[NV], g_py[NV], g_pz[NV]; // screen coords + ndc z
__device__ float g_iw[NV], g_wcl[NV];          // inv_w and clip w
__device__ float g_vcol[NV * NCH];             // per-vertex 11-ch color

// hot face data, SoA float4
__device__ float4 g_hA[NF];   // bx, by, cx, cy
__device__ float4 g_hB[NF];   // d0x, d0y, d1x, d1y
__device__ float4 g_hC[NF];   // inv_area, z0, z1, z2
__device__ float4 g_iw4[NF];  // iw0, iw1, iw2, pad   (cold, resolve only)
__device__ float4 g_bb4[NF];  // bbox x0, x1, y0, y1

__device__ unsigned long long g_zkey[IMG_H * IMG_W];  // (ordered_depth<<32)|faceidx

struct Proj { float m[16]; };

__device__ __forceinline__ unsigned int ford(float d) {
    unsigned int b = __float_as_uint(d);
    return (b & 0x80000000u) ? ~b : (b | 0x80000000u);   // monotone float->uint
}

// ---------------- kernels ----------------
__global__ void k_facenorm(const float* __restrict__ verts,
                           const int* __restrict__ faces) {
    int f = blockIdx.x * blockDim.x + threadIdx.x;
    if (f >= NF) return;
    int i0 = faces[3 * f + 0], i1 = faces[3 * f + 1], i2 = faces[3 * f + 2];
    float ax = verts[3 * i0], ay = verts[3 * i0 + 1], az = verts[3 * i0 + 2];
    float bx = verts[3 * i1], by = verts[3 * i1 + 1], bz = verts[3 * i1 + 2];
    float cx = verts[3 * i2], cy = verts[3 * i2 + 1], cz = verts[3 * i2 + 2];
    float e1x = bx - ax, e1y = by - ay, e1z = bz - az;
    float e2x = cx - ax, e2y = cy - ay, e2z = cz - az;
    float nx = e1y * e2z - e1z * e2y;
    float ny = e1z * e2x - e1x * e2z;
    float nz = e1x * e2y - e1y * e2x;
    float nrm = sqrtf(nx * nx + ny * ny + nz * nz);
    nrm = fmaxf(nrm, 1e-12f);
    nx /= nrm; ny /= nrm; nz /= nrm;
    atomicAdd(&g_vn[3 * i0 + 0], nx); atomicAdd(&g_vn[3 * i0 + 1], ny); atomicAdd(&g_vn[3 * i0 + 2], nz);
    atomicAdd(&g_vn[3 * i1 + 0], nx); atomicAdd(&g_vn[3 * i1 + 1], ny); atomicAdd(&g_vn[3 * i1 + 2], nz);
    atomicAdd(&g_vn[3 * i2 + 0], nx); atomicAdd(&g_vn[3 * i2 + 1], ny); atomicAdd(&g_vn[3 * i2 + 2], nz);
}

__global__ void k_vertex(const float* __restrict__ verts,
                         const float* __restrict__ pose, Proj P) {
    int v = blockIdx.x * blockDim.x + threadIdx.x;
    if (v >= NV) return;
    float x = verts[3 * v], y = verts[3 * v + 1], z = verts[3 * v + 2];
    float p[16];
    #pragma unroll
    for (int i = 0; i < 16; i++) p[i] = pose[i];

    float wx = p[0] * x + p[1] * y + p[2]  * z + p[3];
    float wy = p[4] * x + p[5] * y + p[6]  * z + p[7];
    float wz = p[8] * x + p[9] * y + p[10] * z + p[11];
    float cam[4];
    cam[0] = wx; cam[1] = -wy; cam[2] = -wz;
    cam[3] = p[12] * x + p[13] * y + p[14] * z + p[15];
    float clip[4];
    #pragma unroll
    for (int j = 0; j < 4; j++) {
        clip[j] = P.m[4 * j + 0] * cam[0] + P.m[4 * j + 1] * cam[1]
                + P.m[4 * j + 2] * cam[2] + P.m[4 * j + 3] * cam[3];
    }
    float wc = clip[3];
    float denw = (fabsf(wc) > 1e-9f) ? wc : 1e-9f;
    float iw = 1.0f / denw;
    float n0 = clip[0] * iw, n1 = clip[1] * iw, n2 = clip[2] * iw;
    g_px[v]  = (n0 + 1.0f) * 0.5f * (float)IMG_W;
    g_py[v]  = (1.0f - n1) * 0.5f * (float)IMG_H;
    g_pz[v]  = n2;
    g_iw[v]  = iw;
    g_wcl[v] = wc;

    float vx = g_vn[3 * v], vy = g_vn[3 * v + 1], vz = g_vn[3 * v + 2];
    float nn = sqrtf(vx * vx + vy * vy + vz * vz);
    nn = fmaxf(nn, 1e-12f);
    vx /= nn; vy /= nn; vz /= nn;

    float* col = &g_vcol[v * NCH];
    col[0] = 1.0f;
    col[1] = wx; col[2] = wy; col[3] = wz;
    col[4] = vx; col[5] = vy; col[6] = vz;
    col[7] = x;  col[8] = y;  col[9] = z; col[10] = 1.0f;
}

__global__ void k_facesetup(const int* __restrict__ faces) {
    int f = blockIdx.x * blockDim.x + threadIdx.x;
    if (f >= NF) return;
    int i0 = faces[3 * f + 0], i1 = faces[3 * f + 1], i2 = faces[3 * f + 2];
    float ax = g_px[i0], ay = g_py[i0];
    float bx = g_px[i1], by = g_py[i1];
    float cx = g_px[i2], cy = g_py[i2];
    bool wok = (g_wcl[i0] > 1e-6f) && (g_wcl[i1] > 1e-6f) && (g_wcl[i2] > 1e-6f);
    float area = (bx - ax) * (cy - ay) - (by - ay) * (cx - ax);
    bool areaok = fabsf(area) > 1e-12f;
    float inv_area = 1.0f / (areaok ? area : 1e-12f);
    bool valid = areaok && wok;

    g_hA[f] = make_float4(bx, by, cx, cy);
    g_hB[f] = make_float4(cy - by, cx - bx, ay - cy, ax - cx);
    g_hC[f] = make_float4(valid ? inv_area : 0.0f,
                          valid ? g_pz[i0] : 3e9f,
                          valid ? g_pz[i1] : 3e9f,
                          valid ? g_pz[i2] : 3e9f);
    g_iw4[f] = make_float4(g_iw[i0], g_iw[i1], g_iw[i2], 0.0f);

    // Reference e0 = -wA, e1 = -wB, e2 = 2 - wC (true barycentrics w):
    // drawn region = triangle reflected through C: {C, 2C-A, 2C-B}.
    float4 bb;
    if (valid) {
        float rax = 2.0f * cx - ax, ray = 2.0f * cy - ay;
        float rbx = 2.0f * cx - bx, rby = 2.0f * cy - by;
        bb.x = fminf(cx, fminf(rax, rbx)) - 0.5f;
        bb.y = fmaxf(cx, fmaxf(rax, rbx)) + 0.5f;
        bb.z = fminf(cy, fminf(ray, rby)) - 0.5f;
        bb.w = fmaxf(cy, fmaxf(ray, rby)) + 0.5f;
    } else {
        bb.x = 1e30f; bb.y = -1e30f; bb.z = 1e30f; bb.w = -1e30f;
    }
    g_bb4[f] = bb;
}

__global__ __launch_bounds__(TSZ * TSZ) void k_raster() {
    __shared__ float4 sA[CHF], sB[CHF], sC[CHF], sbb[CHF];

    int tx = threadIdx.x, ty = threadIdx.y;
    int x = blockIdx.x * TSZ + tx;
    int y = blockIdx.y * TSZ + ty;
    float X = (float)x + 0.5f, Y = (float)y + 0.5f;
    int tid = ty * TSZ + tx;
    int lane = tid & 31;
    int warp = tid >> 5;          // warp covers rows {2w, 2w+1}

    float tX0 = (float)(blockIdx.x * TSZ) + 0.5f, tX1 = tX0 + (float)(TSZ - 1);
    float wY0 = (float)(blockIdx.y * TSZ + warp * 2) + 0.5f;
    float wY1 = wY0 + 1.0f;

    int fbeg = blockIdx.z * FPS;

    float best = 1e9f;
    int bf = -1;

    for (int base = fbeg; base < fbeg + FPS; base += CHF) {
        // stage chunk: 128 faces * 4 float4 = 512 float4, 2 per thread
        if (tid < CHF) { sA[tid] = g_hA[base + tid]; sbb[tid] = g_bb4[base + tid]; }
        else { int t = tid - CHF; sB[t] = g_hB[base + t]; sC[t] = g_hC[base + t]; }
        #pragma unroll
        for (int r = 0; r < 2; r++) {
            int t = tid; // second half
            (void)r;
        }
        // remaining halves
        if (tid < CHF) { sB[tid] = g_hB[base + tid]; }
        else { int t = tid - CHF; sA[t] = g_hA[base + t]; sbb[t] = g_bb4[base + t]; }
        if (tid < CHF) { sC[tid] = g_hC[base + tid]; }
        __syncthreads();

        #pragma unroll
        for (int sub = 0; sub < CHF; sub += 32) {
            float4 bb = sbb[sub + lane];
            bool hit = !(bb.y < tX0 || bb.x > tX1 || bb.w < wY0 || bb.z > wY1);
            unsigned m = __ballot_sync(0xffffffffu, hit);
            while (m) {
                int j = sub + (__ffs(m) - 1);
                m &= m - 1;
                float4 A = sA[j], B = sB[j], C = sC[j];   // warp-broadcast LDS
                float e0 = ((X - A.x) * B.x - (Y - A.y) * B.y) * C.x;
                float e1 = ((X - A.z) * B.z - (Y - A.w) * B.w) * C.x;
                float e2 = 1.0f - e0 - e1;
                float depth = e0 * C.y + e1 * C.z + e2 * C.w;
                bool inside = (e0 >= 0.0f) & (e1 >= 0.0f) & (e2 >= 0.0f)
                            & (depth >= -1.0f) & (depth <= 1.0f);
                if (inside && depth < best) { best = depth; bf = base + j; }
            }
        }
        __syncthreads();
    }

    if (bf >= 0) {
        unsigned long long key = ((unsigned long long)ford(best) << 32) | (unsigned)bf;
        atomicMin(&g_zkey[(size_t)y * IMG_W + x], key);
    }
}

__global__ void k_resolve(const int* __restrict__ faces, float* __restrict__ out) {
    int i = blockIdx.x * blockDim.x + threadIdx.x;
    if (i >= IMG_H * IMG_W) return;
    unsigned long long key = g_zkey[i];
    float col[NCH];
    if (key != 0xFFFFFFFFFFFFFFFFull) {
        int bf = (int)(key & 0xFFFFFFFFu);
        int x = i % IMG_W, y = i / IMG_W;
        float X = (float)x + 0.5f, Y = (float)y + 0.5f;
        float4 A = g_hA[bf], B = g_hB[bf], C = g_hC[bf], W = g_iw4[bf];
        float e0 = ((X - A.x) * B.x - (Y - A.y) * B.y) * C.x;
        float e1 = ((X - A.z) * B.z - (Y - A.w) * B.w) * C.x;
        float e2 = 1.0f - e0 - e1;
        float p0 = e0 * W.x, p1 = e1 * W.y, p2 = e2 * W.z;
        float den = p0 + p1 + p2;
        den = (fabsf(den) > 1e-12f) ? den : 1e-12f;
        float w0 = p0 / den, w1 = p1 / den, w2 = p2 / den;
        int i0 = faces[3 * bf + 0], i1 = faces[3 * bf + 1], i2 = faces[3 * bf + 2];
        const float* c0 = &g_vcol[i0 * NCH];
        const float* c1 = &g_vcol[i1 * NCH];
        const float* c2 = &g_vcol[i2 * NCH];
        #pragma unroll
        for (int c = 0; c < NCH; c++)
            col[c] = w0 * c0[c] + w1 * c1[c] + w2 * c2[c];
    } else {
        #pragma unroll
        for (int c = 0; c < NCH; c++) col[c] = 0.0f;
    }
    float* o = out + (size_t)i * NCH;
    #pragma unroll
    for (int c = 0; c < NCH; c++) o[c] = col[c];
}

// ---------------- host ----------------
static Proj build_proj_host() {
    const double fx = 286.2057, sk = 0.0, cxx = 162.6306;
    const double fy = 286.7852, cyy = 121.0245;
    const double w = IMG_W, h = IMG_H;
    const double nc = 0.1, fc = 10.0;
    double q  = -(fc + nc) / (fc - nc);
    double qn = -2.0 * fc * nc / (fc - nc);
    double m[4][4] = {
        {2.0 * fx / w, -2.0 * sk / w, (-2.0 * cxx + w) / w, 0.0},
        {0.0, -2.0 * fy / h, (-2.0 * cyy + h) / h, 0.0},
        {0.0, 0.0, q, qn},
        {0.0, 0.0, -1.0, 0.0}
    };
    for (int k = 0; k < 4; k++) m[1][k] *= -1.0;
    Proj P;
    for (int j = 0; j < 4; j++)
        for (int k = 0; k < 4; k++)
            P.m[4 * j + k] = (float)m[j][k];
    return P;
}

extern "C" void kernel_launch(void* const* d_in, const int* in_sizes, int n_in,
                              void* d_out, int out_size) {
    const float* verts = nullptr;
    const int*   faces = nullptr;
    const float* pose  = nullptr;
    for (int i = 0; i < n_in; i++) {
        if (in_sizes[i] == NV * 3)       verts = (const float*)d_in[i];
        else if (in_sizes[i] == NF * 3)  faces = (const int*)d_in[i];
        else if (in_sizes[i] == 16)      pose  = (const float*)d_in[i];
    }
    float* out = (float*)d_out;    // (1, 240, 320, 11)
    (void)out_size;

    Proj P = build_proj_host();

    void* vn_ptr = nullptr;
    void* zk_ptr = nullptr;
    cudaGetSymbolAddress(&vn_ptr, g_vn);
    cudaGetSymbolAddress(&zk_ptr, g_zkey);
    cudaMemsetAsync(vn_ptr, 0, NV * 3 * sizeof(float));
    cudaMemsetAsync(zk_ptr, 0xFF, IMG_H * IMG_W * sizeof(unsigned long long));

    k_facenorm<<<(NF + 127) / 128, 128>>>(verts, faces);
    k_vertex<<<(NV + 255) / 256, 256>>>(verts, pose, P);
    k_facesetup<<<(NF + 127) / 128, 128>>>(faces);
    dim3 grid(IMG_W / TSZ, IMG_H / TSZ, SLICES);
    dim3 blk(TSZ, TSZ);
    k_raster<<<grid, blk>>>();
    k_resolve<<<(IMG_H * IMG_W + 255) / 256, 256>>>(faces, out);
}

// round 14
// speedup vs baseline: 1.2240x; 1.2060x over previous
#include <cuda_runtime.h>
#include <math.h>
#include <stdint.h>

#define IMG_H 240
#define IMG_W 320
#define NV 12288
#define NF 4096
#define NCH 11
#define TSZ 16
#define CHF 128      // faces per smem chunk
#define SLICES 4
#define FPS (NF / SLICES)   // 1024 faces per slice

// ---------------- device scratch (no allocations allowed) ----------------
__device__ float g_vn[NV * 3];                 // vertex normal accumulators
__device__ float g_px[NV], g_py[NV], g_pz[NV]; // screen coords + ndc z
__device__ float g_iw[NV], g_wcl[NV];          // inv_w and clip w
__device__ float g_vcol[NV * NCH];             // per-vertex 11-ch color

// hot face data, SoA float4
__device__ float4 g_hA[NF];   // bx, by, cx, cy   (NaN if invalid -> culled)
__device__ float4 g_hB[NF];   // d0x, d0y, d1x, d1y
__device__ float4 g_hC[NF];   // inv_area, z0, z1, z2
__device__ float4 g_iw4[NF];  // iw0, iw1, iw2, pad   (cold, resolve only)

__device__ unsigned long long g_zkey[IMG_H * IMG_W];  // (ordered_depth<<32)|faceidx

struct Proj { float m[16]; };

__device__ __forceinline__ unsigned int ford(float d) {
    unsigned int b = __float_as_uint(d);
    return (b & 0x80000000u) ? ~b : (b | 0x80000000u);   // monotone float->uint
}

// ---------------- kernels ----------------
__global__ void k_facenorm(const float* __restrict__ verts,
                           const int* __restrict__ faces) {
    int f = blockIdx.x * blockDim.x + threadIdx.x;
    if (f >= NF) return;
    int i0 = faces[3 * f + 0], i1 = faces[3 * f + 1], i2 = faces[3 * f + 2];
    float ax = verts[3 * i0], ay = verts[3 * i0 + 1], az = verts[3 * i0 + 2];
    float bx = verts[3 * i1], by = verts[3 * i1 + 1], bz = verts[3 * i1 + 2];
    float cx = verts[3 * i2], cy = verts[3 * i2 + 1], cz = verts[3 * i2 + 2];
    float e1x = bx - ax, e1y = by - ay, e1z = bz - az;
    float e2x = cx - ax, e2y = cy - ay, e2z = cz - az;
    float nx = e1y * e2z - e1z * e2y;
    float ny = e1z * e2x - e1x * e2z;
    float nz = e1x * e2y - e1y * e2x;
    float nrm = sqrtf(nx * nx + ny * ny + nz * nz);
    nrm = fmaxf(nrm, 1e-12f);
    nx /= nrm; ny /= nrm; nz /= nrm;
    atomicAdd(&g_vn[3 * i0 + 0], nx); atomicAdd(&g_vn[3 * i0 + 1], ny); atomicAdd(&g_vn[3 * i0 + 2], nz);
    atomicAdd(&g_vn[3 * i1 + 0], nx); atomicAdd(&g_vn[3 * i1 + 1], ny); atomicAdd(&g_vn[3 * i1 + 2], nz);
    atomicAdd(&g_vn[3 * i2 + 0], nx); atomicAdd(&g_vn[3 * i2 + 1], ny); atomicAdd(&g_vn[3 * i2 + 2], nz);
}

__global__ void k_vertex(const float* __restrict__ verts,
                         const float* __restrict__ pose, Proj P) {
    int v = blockIdx.x * blockDim.x + threadIdx.x;
    if (v >= NV) return;
    float x = verts[3 * v], y = verts[3 * v + 1], z = verts[3 * v + 2];
    float p[16];
    #pragma unroll
    for (int i = 0; i < 16; i++) p[i] = pose[i];

    float wx = p[0] * x + p[1] * y + p[2]  * z + p[3];
    float wy = p[4] * x + p[5] * y + p[6]  * z + p[7];
    float wz = p[8] * x + p[9] * y + p[10] * z + p[11];
    float cam[4];
    cam[0] = wx; cam[1] = -wy; cam[2] = -wz;
    cam[3] = p[12] * x + p[13] * y + p[14] * z + p[15];
    float clip[4];
    #pragma unroll
    for (int j = 0; j < 4; j++) {
        clip[j] = P.m[4 * j + 0] * cam[0] + P.m[4 * j + 1] * cam[1]
                + P.m[4 * j + 2] * cam[2] + P.m[4 * j + 3] * cam[3];
    }
    float wc = clip[3];
    float denw = (fabsf(wc) > 1e-9f) ? wc : 1e-9f;
    float iw = 1.0f / denw;
    float n0 = clip[0] * iw, n1 = clip[1] * iw, n2 = clip[2] * iw;
    g_px[v]  = (n0 + 1.0f) * 0.5f * (float)IMG_W;
    g_py[v]  = (1.0f - n1) * 0.5f * (float)IMG_H;
    g_pz[v]  = n2;
    g_iw[v]  = iw;
    g_wcl[v] = wc;

    float vx = g_vn[3 * v], vy = g_vn[3 * v + 1], vz = g_vn[3 * v + 2];
    float nn = sqrtf(vx * vx + vy * vy + vz * vz);
    nn = fmaxf(nn, 1e-12f);
    vx /= nn; vy /= nn; vz /= nn;

    float* col = &g_vcol[v * NCH];
    col[0] = 1.0f;
    col[1] = wx; col[2] = wy; col[3] = wz;
    col[4] = vx; col[5] = vy; col[6] = vz;
    col[7] = x;  col[8] = y;  col[9] = z; col[10] = 1.0f;
}

__global__ void k_facesetup(const int* __restrict__ faces) {
    int f = blockIdx.x * blockDim.x + threadIdx.x;
    if (f >= NF) return;
    int i0 = faces[3 * f + 0], i1 = faces[3 * f + 1], i2 = faces[3 * f + 2];
    float ax = g_px[i0], ay = g_py[i0];
    float bx = g_px[i1], by = g_py[i1];
    float cx = g_px[i2], cy = g_py[i2];
    bool wok = (g_wcl[i0] > 1e-6f) && (g_wcl[i1] > 1e-6f) && (g_wcl[i2] > 1e-6f);
    float area = (bx - ax) * (cy - ay) - (by - ay) * (cx - ax);
    bool areaok = fabsf(area) > 1e-12f;
    float inv_area = 1.0f / (areaok ? area : 1e-12f);
    bool valid = areaok && wok;

    float nanf_ = __int_as_float(0x7fc00000);
    // Invalid faces: NaN positions make every edge-cull comparison false -> culled
    // everywhere, matching reference tval=false (no pixels drawn).
    g_hA[f] = valid ? make_float4(bx, by, cx, cy)
                    : make_float4(nanf_, nanf_, nanf_, nanf_);
    g_hB[f] = make_float4(cy - by, cx - bx, ay - cy, ax - cx);
    g_hC[f] = make_float4(valid ? inv_area : 0.0f,
                          valid ? g_pz[i0] : 3e9f,
                          valid ? g_pz[i1] : 3e9f,
                          valid ? g_pz[i2] : 3e9f);
    g_iw4[f] = make_float4(g_iw[i0], g_iw[i1], g_iw[i2], 0.0f);
}

__global__ __launch_bounds__(TSZ * TSZ) void k_raster() {
    __shared__ float4 sA[CHF], sB[CHF], sC[CHF];

    int tx = threadIdx.x, ty = threadIdx.y;
    int x = blockIdx.x * TSZ + tx;
    int y = blockIdx.y * TSZ + ty;
    float X = (float)x + 0.5f, Y = (float)y + 0.5f;
    int tid = ty * TSZ + tx;
    int lane = tid & 31;
    int warp = tid >> 5;          // warp covers rows {2w, 2w+1}

    // strip rect extended by 1px for a conservative cull margin
    float xlo = (float)(blockIdx.x * TSZ) + 0.5f - 1.0f;
    float xhi = xlo + (float)(TSZ - 1) + 2.0f;
    float ylo = (float)(blockIdx.y * TSZ + warp * 2) + 0.5f - 1.0f;
    float yhi = ylo + 1.0f + 2.0f;

    int fbeg = blockIdx.z * FPS;

    float best = 1e9f;
    int bf = -1;

    for (int base = fbeg; base < fbeg + FPS; base += CHF) {
        for (int k = tid; k < 3 * CHF; k += TSZ * TSZ) {
            int a = k >> 7, o = k & (CHF - 1);
            if (a == 0)      sA[o] = g_hA[base + o];
            else if (a == 1) sB[o] = g_hB[base + o];
            else             sC[o] = g_hC[base + o];
        }
        __syncthreads();

        #pragma unroll
        for (int sub = 0; sub < CHF; sub += 32) {
            // exact half-plane cull: one face per lane vs this warp's strip
            int fj = sub + lane;
            float4 A = sA[fj], B = sB[fj], C = sC[fj];
            float ia = C.x;
            float gx0 = B.x * ia, gy0 = -B.y * ia;
            float gx1 = B.z * ia, gy1 = -B.w * ia;
            float xm, ym;
            xm = (gx0 >= 0.f) ? xhi : xlo;
            ym = (gy0 >= 0.f) ? yhi : ylo;
            float E0 = ((xm - A.x) * B.x - (ym - A.y) * B.y) * ia;
            xm = (gx1 >= 0.f) ? xhi : xlo;
            ym = (gy1 >= 0.f) ? yhi : ylo;
            float E1 = ((xm - A.z) * B.z - (ym - A.w) * B.w) * ia;
            xm = (gx0 + gx1 >= 0.f) ? xlo : xhi;   // minimize e0+e1 -> maximize e2
            ym = (gy0 + gy1 >= 0.f) ? ylo : yhi;
            float s = ((xm - A.x) * B.x - (ym - A.y) * B.y) * ia
                    + ((xm - A.z) * B.z - (ym - A.w) * B.w) * ia;
            bool hit = (E0 >= 0.f) & (E1 >= 0.f) & (s <= 1.0f);

            unsigned m = __ballot_sync(0xffffffffu, hit);
            while (m) {
                int j = sub + (__ffs(m) - 1);
                m &= m - 1;
                float4 Aj = sA[j], Bj = sB[j], Cj = sC[j];   // warp-broadcast LDS
                float e0 = ((X - Aj.x) * Bj.x - (Y - Aj.y) * Bj.y) * Cj.x;
                float e1 = ((X - Aj.z) * Bj.z - (Y - Aj.w) * Bj.w) * Cj.x;
                float e2 = 1.0f - e0 - e1;
                float depth = e0 * Cj.y + e1 * Cj.z + e2 * Cj.w;
                bool inside = (e0 >= 0.0f) & (e1 >= 0.0f) & (e2 >= 0.0f)
                            & (depth >= -1.0f) & (depth <= 1.0f);
                if (inside && depth < best) { best = depth; bf = base + j; }
            }
        }
        __syncthreads();
    }

    if (bf >= 0) {
        unsigned long long key = ((unsigned long long)ford(best) << 32) | (unsigned)bf;
        atomicMin(&g_zkey[(size_t)y * IMG_W + x], key);
    }
}

__global__ void k_resolve(const int* __restrict__ faces, float* __restrict__ out) {
    int i = blockIdx.x * blockDim.x + threadIdx.x;
    if (i >= IMG_H * IMG_W) return;
    unsigned long long key = g_zkey[i];
    float col[NCH];
    if (key != 0xFFFFFFFFFFFFFFFFull) {
        int bf = (int)(key & 0xFFFFFFFFu);
        int x = i % IMG_W, y = i / IMG_W;
        float X = (float)x + 0.5f, Y = (float)y + 0.5f;
        float4 A = g_hA[bf], B = g_hB[bf], C = g_hC[bf], W = g_iw4[bf];
        float e0 = ((X - A.x) * B.x - (Y - A.y) * B.y) * C.x;
        float e1 = ((X - A.z) * B.z - (Y - A.w) * B.w) * C.x;
        float e2 = 1.0f - e0 - e1;
        float p0 = e0 * W.x, p1 = e1 * W.y, p2 = e2 * W.z;
        float den = p0 + p1 + p2;
        den = (fabsf(den) > 1e-12f) ? den : 1e-12f;
        float w0 = p0 / den, w1 = p1 / den, w2 = p2 / den;
        int i0 = faces[3 * bf + 0], i1 = faces[3 * bf + 1], i2 = faces[3 * bf + 2];
        const float* c0 = &g_vcol[i0 * NCH];
        const float* c1 = &g_vcol[i1 * NCH];
        const float* c2 = &g_vcol[i2 * NCH];
        #pragma unroll
        for (int c = 0; c < NCH; c++)
            col[c] = w0 * c0[c] + w1 * c1[c] + w2 * c2[c];
    } else {
        #pragma unroll
        for (int c = 0; c < NCH; c++) col[c] = 0.0f;
    }
    float* o = out + (size_t)i * NCH;
    #pragma unroll
    for (int c = 0; c < NCH; c++) o[c] = col[c];
}

// ---------------- host ----------------
static Proj build_proj_host() {
    const double fx = 286.2057, sk = 0.0, cxx = 162.6306;
    const double fy = 286.7852, cyy = 121.0245;
    const double w = IMG_W, h = IMG_H;
    const double nc = 0.1, fc = 10.0;
    double q  = -(fc + nc) / (fc - nc);
    double qn = -2.0 * fc * nc / (fc - nc);
    double m[4][4] = {
        {2.0 * fx / w, -2.0 * sk / w, (-2.0 * cxx + w) / w, 0.0},
        {0.0, -2.0 * fy / h, (-2.0 * cyy + h) / h, 0.0},
        {0.0, 0.0, q, qn},
        {0.0, 0.0, -1.0, 0.0}
    };
    for (int k = 0; k < 4; k++) m[1][k] *= -1.0;
    Proj P;
    for (int j = 0; j < 4; j++)
        for (int k = 0; k < 4; k++)
            P.m[4 * j + k] = (float)m[j][k];
    return P;
}

extern "C" void kernel_launch(void* const* d_in, const int* in_sizes, int n_in,
                              void* d_out, int out_size) {
    const float* verts = nullptr;
    const int*   faces = nullptr;
    const float* pose  = nullptr;
    for (int i = 0; i < n_in; i++) {
        if (in_sizes[i] == NV * 3)       verts = (const float*)d_in[i];
        else if (in_sizes[i] == NF * 3)  faces = (const int*)d_in[i];
        else if (in_sizes[i] == 16)      pose  = (const float*)d_in[i];
    }
    float* out = (float*)d_out;    // (1, 240, 320, 11)
    (void)out_size;

    Proj P = build_proj_host();

    void* vn_ptr = nullptr;
    void* zk_ptr = nullptr;
    cudaGetSymbolAddress(&vn_ptr, g_vn);
    cudaGetSymbolAddress(&zk_ptr, g_zkey);
    cudaMemsetAsync(vn_ptr, 0, NV * 3 * sizeof(float));
    cudaMemsetAsync(zk_ptr, 0xFF, IMG_H * IMG_W * sizeof(unsigned long long));

    k_facenorm<<<(NF + 127) / 128, 128>>>(verts, faces);
    k_vertex<<<(NV + 255) / 256, 256>>>(verts, pose, P);
    k_facesetup<<<(NF + 127) / 128, 128>>>(faces);
    dim3 grid(IMG_W / TSZ, IMG_H / TSZ, SLICES);
    dim3 blk(TSZ, TSZ);
    k_raster<<<grid, blk>>>();
    k_resolve<<<(IMG_H * IMG_W + 255) / 256, 256>>>(faces, out);
}

// round 15
// speedup vs baseline: 1.3154x; 1.0747x over previous
#include <cuda_runtime.h>
#include <math.h>
#include <stdint.h>

#define IMG_H 240
#define IMG_W 320
#define NV 12288
#define NF 4096
#define NCH 11
#define TSZ 16
#define CHF 128      // faces per smem chunk
#define SLICES 2
#define FPS (NF / SLICES)   // 2048 faces per slice

// ---------------- device scratch (no allocations allowed) ----------------
__device__ float g_vn[NV * 3];                 // vertex normal accumulators
__device__ float g_px[NV], g_py[NV], g_pz[NV]; // screen coords + ndc z
__device__ float g_iw[NV], g_wcl[NV];          // inv_w and clip w
__device__ float g_vcol[NV * NCH];             // per-vertex 11-ch color

// hot face data, SoA float4
__device__ float4 g_hA[NF];   // bx, by, cx, cy   (NaN if invalid -> culled)
__device__ float4 g_hB[NF];   // d0x, d0y, d1x, d1y
__device__ float4 g_hC[NF];   // inv_area, z0, z1, z2
__device__ float4 g_iw4[NF];  // iw0, iw1, iw2, pad   (cold, resolve only)

__device__ unsigned long long g_zkey[IMG_H * IMG_W];  // (ordered_depth<<32)|faceidx

struct Proj { float m[16]; };

__device__ __forceinline__ unsigned int ford(float d) {
    unsigned int b = __float_as_uint(d);
    return (b & 0x80000000u) ? ~b : (b | 0x80000000u);   // monotone float->uint
}

// ---------------- kernels ----------------
__global__ void k_facenorm(const float* __restrict__ verts,
                           const int* __restrict__ faces) {
    int f = blockIdx.x * blockDim.x + threadIdx.x;
    if (f >= NF) return;
    int i0 = faces[3 * f + 0], i1 = faces[3 * f + 1], i2 = faces[3 * f + 2];
    float ax = verts[3 * i0], ay = verts[3 * i0 + 1], az = verts[3 * i0 + 2];
    float bx = verts[3 * i1], by = verts[3 * i1 + 1], bz = verts[3 * i1 + 2];
    float cx = verts[3 * i2], cy = verts[3 * i2 + 1], cz = verts[3 * i2 + 2];
    float e1x = bx - ax, e1y = by - ay, e1z = bz - az;
    float e2x = cx - ax, e2y = cy - ay, e2z = cz - az;
    float nx = e1y * e2z - e1z * e2y;
    float ny = e1z * e2x - e1x * e2z;
    float nz = e1x * e2y - e1y * e2x;
    float nrm = sqrtf(nx * nx + ny * ny + nz * nz);
    nrm = fmaxf(nrm, 1e-12f);
    nx /= nrm; ny /= nrm; nz /= nrm;
    atomicAdd(&g_vn[3 * i0 + 0], nx); atomicAdd(&g_vn[3 * i0 + 1], ny); atomicAdd(&g_vn[3 * i0 + 2], nz);
    atomicAdd(&g_vn[3 * i1 + 0], nx); atomicAdd(&g_vn[3 * i1 + 1], ny); atomicAdd(&g_vn[3 * i1 + 2], nz);
    atomicAdd(&g_vn[3 * i2 + 0], nx); atomicAdd(&g_vn[3 * i2 + 1], ny); atomicAdd(&g_vn[3 * i2 + 2], nz);
}

__global__ void k_vertex(const float* __restrict__ verts,
                         const float* __restrict__ pose, Proj P) {
    int v = blockIdx.x * blockDim.x + threadIdx.x;
    if (v >= NV) return;
    float x = verts[3 * v], y = verts[3 * v + 1], z = verts[3 * v + 2];
    float p[16];
    #pragma unroll
    for (int i = 0; i < 16; i++) p[i] = pose[i];

    float wx = p[0] * x + p[1] * y + p[2]  * z + p[3];
    float wy = p[4] * x + p[5] * y + p[6]  * z + p[7];
    float wz = p[8] * x + p[9] * y + p[10] * z + p[11];
    float cam[4];
    cam[0] = wx; cam[1] = -wy; cam[2] = -wz;
    cam[3] = p[12] * x + p[13] * y + p[14] * z + p[15];
    float clip[4];
    #pragma unroll
    for (int j = 0; j < 4; j++) {
        clip[j] = P.m[4 * j + 0] * cam[0] + P.m[4 * j + 1] * cam[1]
                + P.m[4 * j + 2] * cam[2] + P.m[4 * j + 3] * cam[3];
    }
    float wc = clip[3];
    float denw = (fabsf(wc) > 1e-9f) ? wc : 1e-9f;
    float iw = 1.0f / denw;
    float n0 = clip[0] * iw, n1 = clip[1] * iw, n2 = clip[2] * iw;
    g_px[v]  = (n0 + 1.0f) * 0.5f * (float)IMG_W;
    g_py[v]  = (1.0f - n1) * 0.5f * (float)IMG_H;
    g_pz[v]  = n2;
    g_iw[v]  = iw;
    g_wcl[v] = wc;

    float vx = g_vn[3 * v], vy = g_vn[3 * v + 1], vz = g_vn[3 * v + 2];
    float nn = sqrtf(vx * vx + vy * vy + vz * vz);
    nn = fmaxf(nn, 1e-12f);
    vx /= nn; vy /= nn; vz /= nn;

    float* col = &g_vcol[v * NCH];
    col[0] = 1.0f;
    col[1] = wx; col[2] = wy; col[3] = wz;
    col[4] = vx; col[5] = vy; col[6] = vz;
    col[7] = x;  col[8] = y;  col[9] = z; col[10] = 1.0f;
}

__global__ void k_facesetup(const int* __restrict__ faces) {
    int f = blockIdx.x * blockDim.x + threadIdx.x;
    if (f >= NF) return;
    int i0 = faces[3 * f + 0], i1 = faces[3 * f + 1], i2 = faces[3 * f + 2];
    float ax = g_px[i0], ay = g_py[i0];
    float bx = g_px[i1], by = g_py[i1];
    float cx = g_px[i2], cy = g_py[i2];
    bool wok = (g_wcl[i0] > 1e-6f) && (g_wcl[i1] > 1e-6f) && (g_wcl[i2] > 1e-6f);
    float area = (bx - ax) * (cy - ay) - (by - ay) * (cx - ax);
    bool areaok = fabsf(area) > 1e-12f;
    float inv_area = 1.0f / (areaok ? area : 1e-12f);
    bool valid = areaok && wok;

    float nanf_ = __int_as_float(0x7fc00000);
    // Invalid faces: NaN positions -> every cull comparison false -> never drawn
    g_hA[f] = valid ? make_float4(bx, by, cx, cy)
                    : make_float4(nanf_, nanf_, nanf_, nanf_);
    g_hB[f] = make_float4(cy - by, cx - bx, ay - cy, ax - cx);
    g_hC[f] = make_float4(valid ? inv_area : 0.0f,
                          valid ? g_pz[i0] : 3e9f,
                          valid ? g_pz[i1] : 3e9f,
                          valid ? g_pz[i2] : 3e9f);
    g_iw4[f] = make_float4(g_iw[i0], g_iw[i1], g_iw[i2], 0.0f);
}

__global__ __launch_bounds__(TSZ * TSZ) void k_raster() {
    __shared__ float4 sA[CHF], sB[CHF], sC[CHF];

    int tx = threadIdx.x, ty = threadIdx.y;
    int x = blockIdx.x * TSZ + tx;
    int y = blockIdx.y * TSZ + ty;
    float X = (float)x + 0.5f, Y = (float)y + 0.5f;
    int tid = ty * TSZ + tx;
    int lane = tid & 31;
    int warp = tid >> 5;          // warp covers rows {2w, 2w+1}

    // strip rect extended by 1px for a conservative cull margin
    float xlo = (float)(blockIdx.x * TSZ) + 0.5f - 1.0f;
    float xhi = xlo + (float)(TSZ - 1) + 2.0f;
    float ylo = (float)(blockIdx.y * TSZ + warp * 2) + 0.5f - 1.0f;
    float yhi = ylo + 1.0f + 2.0f;

    int fbeg = blockIdx.z * FPS;

    float best = 1e9f;
    int bf = -1;

    for (int base = fbeg; base < fbeg + FPS; base += CHF) {
        for (int k = tid; k < 3 * CHF; k += TSZ * TSZ) {
            int a = k >> 7, o = k & (CHF - 1);
            if (a == 0)      sA[o] = g_hA[base + o];
            else if (a == 1) sB[o] = g_hB[base + o];
            else             sC[o] = g_hC[base + o];
        }
        __syncthreads();

        // warp-uniform stale upper bound on best (stale => conservative => exact)
        float bm = best;
        #pragma unroll
        for (int o = 16; o >= 1; o >>= 1)
            bm = fmaxf(bm, __shfl_xor_sync(0xffffffffu, bm, o));
        bm += 0.01f;   // >> any depth-vs-zmin rounding slack

        #pragma unroll
        for (int sub = 0; sub < CHF; sub += 32) {
            // exact half-plane cull + early-z: one face per lane vs warp strip
            int fj = sub + lane;
            float4 A = sA[fj], B = sB[fj], C = sC[fj];
            float ia = C.x;
            float zmin = fminf(C.y, fminf(C.z, C.w));
            float gx0 = B.x * ia, gy0 = -B.y * ia;
            float gx1 = B.z * ia, gy1 = -B.w * ia;
            float xm, ym;
            xm = (gx0 >= 0.f) ? xhi : xlo;
            ym = (gy0 >= 0.f) ? yhi : ylo;
            float E0 = ((xm - A.x) * B.x - (ym - A.y) * B.y) * ia;
            xm = (gx1 >= 0.f) ? xhi : xlo;
            ym = (gy1 >= 0.f) ? yhi : ylo;
            float E1 = ((xm - A.z) * B.z - (ym - A.w) * B.w) * ia;
            xm = (gx0 + gx1 >= 0.f) ? xlo : xhi;   // minimize e0+e1 -> maximize e2
            ym = (gy0 + gy1 >= 0.f) ? ylo : yhi;
            float s = ((xm - A.x) * B.x - (ym - A.y) * B.y) * ia
                    + ((xm - A.z) * B.z - (ym - A.w) * B.w) * ia;
            bool hit = (E0 >= 0.f) & (E1 >= 0.f) & (s <= 1.0f) & (zmin <= bm);

            unsigned m = __ballot_sync(0xffffffffu, hit);
            while (m) {
                int j = sub + (__ffs(m) - 1);
                m &= m - 1;
                float4 Aj = sA[j], Bj = sB[j], Cj = sC[j];   // warp-broadcast LDS
                float e0 = ((X - Aj.x) * Bj.x - (Y - Aj.y) * Bj.y) * Cj.x;
                float e1 = ((X - Aj.z) * Bj.z - (Y - Aj.w) * Bj.w) * Cj.x;
                float e2 = 1.0f - e0 - e1;
                float depth = e0 * Cj.y + e1 * Cj.z + e2 * Cj.w;
                bool inside = (e0 >= 0.0f) & (e1 >= 0.0f) & (e2 >= 0.0f)
                            & (depth >= -1.0f) & (depth <= 1.0f);
                if (inside && depth < best) { best = depth; bf = base + j; }
            }
        }
        __syncthreads();
    }

    if (bf >= 0) {
        unsigned long long key = ((unsigned long long)ford(best) << 32) | (unsigned)bf;
        atomicMin(&g_zkey[(size_t)y * IMG_W + x], key);
    }
}

__global__ void k_resolve(const int* __restrict__ faces, float* __restrict__ out) {
    int i = blockIdx.x * blockDim.x + threadIdx.x;
    if (i >= IMG_H * IMG_W) return;
    unsigned long long key = g_zkey[i];
    float col[NCH];
    if (key != 0xFFFFFFFFFFFFFFFFull) {
        int bf = (int)(key & 0xFFFFFFFFu);
        int x = i % IMG_W, y = i / IMG_W;
        float X = (float)x + 0.5f, Y = (float)y + 0.5f;
        float4 A = g_hA[bf], B = g_hB[bf], C = g_hC[bf], W = g_iw4[bf];
        float e0 = ((X - A.x) * B.x - (Y - A.y) * B.y) * C.x;
        float e1 = ((X - A.z) * B.z - (Y - A.w) * B.w) * C.x;
        float e2 = 1.0f - e0 - e1;
        float p0 = e0 * W.x, p1 = e1 * W.y, p2 = e2 * W.z;
        float den = p0 + p1 + p2;
        den = (fabsf(den) > 1e-12f) ? den : 1e-12f;
        float w0 = p0 / den, w1 = p1 / den, w2 = p2 / den;
        int i0 = faces[3 * bf + 0], i1 = faces[3 * bf + 1], i2 = faces[3 * bf + 2];
        const float* c0 = &g_vcol[i0 * NCH];
        const float* c1 = &g_vcol[i1 * NCH];
        const float* c2 = &g_vcol[i2 * NCH];
        #pragma unroll
        for (int c = 0; c < NCH; c++)
            col[c] = w0 * c0[c] + w1 * c1[c] + w2 * c2[c];
    } else {
        #pragma unroll
        for (int c = 0; c < NCH; c++) col[c] = 0.0f;
    }
    float* o = out + (size_t)i * NCH;
    #pragma unroll
    for (int c = 0; c < NCH; c++) o[c] = col[c];
}

// ---------------- host ----------------
static Proj build_proj_host() {
    const double fx = 286.2057, sk = 0.0, cxx = 162.6306;
    const double fy = 286.7852, cyy = 121.0245;
    const double w = IMG_W, h = IMG_H;
    const double nc = 0.1, fc = 10.0;
    double q  = -(fc + nc) / (fc - nc);
    double qn = -2.0 * fc * nc / (fc - nc);
    double m[4][4] = {
        {2.0 * fx / w, -2.0 * sk / w, (-2.0 * cxx + w) / w, 0.0},
        {0.0, -2.0 * fy / h, (-2.0 * cyy + h) / h, 0.0},
        {0.0, 0.0, q, qn},
        {0.0, 0.0, -1.0, 0.0}
    };
    for (int k = 0; k < 4; k++) m[1][k] *= -1.0;
    Proj P;
    for (int j = 0; j < 4; j++)
        for (int k = 0; k < 4; k++)
            P.m[4 * j + k] = (float)m[j][k];
    return P;
}

extern "C" void kernel_launch(void* const* d_in, const int* in_sizes, int n_in,
                              void* d_out, int out_size) {
    const float* verts = nullptr;
    const int*   faces = nullptr;
    const float* pose  = nullptr;
    for (int i = 0; i < n_in; i++) {
        if (in_sizes[i] == NV * 3)       verts = (const float*)d_in[i];
        else if (in_sizes[i] == NF * 3)  faces = (const int*)d_in[i];
        else if (in_sizes[i] == 16)      pose  = (const float*)d_in[i];
    }
    float* out = (float*)d_out;    // (1, 240, 320, 11)
    (void)out_size;

    Proj P = build_proj_host();

    void* vn_ptr = nullptr;
    void* zk_ptr = nullptr;
    cudaGetSymbolAddress(&vn_ptr, g_vn);
    cudaGetSymbolAddress(&zk_ptr, g_zkey);
    cudaMemsetAsync(vn_ptr, 0, NV * 3 * sizeof(float));
    cudaMemsetAsync(zk_ptr, 0xFF, IMG_H * IMG_W * sizeof(unsigned long long));

    k_facenorm<<<(NF + 127) / 128, 128>>>(verts, faces);
    k_vertex<<<(NV + 255) / 256, 256>>>(verts, pose, P);
    k_facesetup<<<(NF + 127) / 128, 128>>>(faces);
    dim3 grid(IMG_W / TSZ, IMG_H / TSZ, SLICES);
    dim3 blk(TSZ, TSZ);
    k_raster<<<grid, blk>>>();
    k_resolve<<<(IMG_H * IMG_W + 255) / 256, 256>>>(faces, out);
}